// round 11
// baseline (speedup 1.0000x reference)
#include <cuda_runtime.h>
#include <cuda_bf16.h>
#include <math.h>
#include <stdint.h>

// Problem constants
#define NN 13
#define BB 2
#define TT 2048
#define DD 1024
#define ROW_F4 (DD / 4)          // 256 float4 per row
#define NTILES (BB * TT)         // 4096
#define THREADS 512
#define GRID 152                 // 1 CTA per SM (GB300: 152 SMs)
#define SLOTS 3                  // pipeline depth: compute 1, 2 in flight
#define EPS 1.1920928955078125e-07f   // FLT_EPSILON

#define CHUNKS (NN * ROW_F4)                 // 3328 float4 per tile
#define SMEM_BYTES (SLOTS * CHUNKS * 16)     // 159744 B

__device__ __forceinline__ void cp_async16(uint32_t smem_addr, const void* gptr) {
    asm volatile("cp.async.cg.shared.global [%0], [%1], 16;\n"
                 :: "r"(smem_addr), "l"(gptr) : "memory");
}

__global__ __launch_bounds__(THREADS, 1)
void attn_res_block_kernel(const float4* __restrict__ V,
                           const float4* __restrict__ rms_w,
                           const float4* __restrict__ w_proj,
                           float4* __restrict__ out)
{
    extern __shared__ float4 sbuf[];            // [SLOTS][NN][ROW_F4]
    __shared__ float s_logit[NN];

    const int tid  = threadIdx.x;
    const int lane = tid & 31;
    const int wid  = tid >> 5;                  // 0..15

    uint32_t sb_a;
    {
        uint64_t t;
        asm("cvta.to.shared.u64 %0, %1;" : "=l"(t) : "l"((void*)sbuf));
        sb_a = (uint32_t)t;
    }

    // Lane-indexed combined weight (rms_weight * w_proj), registers for the
    // whole loop. Phase-1 row view: lane covers float4 columns k*32+lane.
    float4 cw[8];
    #pragma unroll
    for (int k = 0; k < 8; k++) {
        float4 a = rms_w[k * 32 + lane];
        float4 b = w_proj[k * 32 + lane];
        cw[k] = make_float4(a.x * b.x, a.y * b.y, a.z * b.z, a.w * b.w);
    }

    // All 512 threads cooperate on the copy: chunk c -> (row c>>8, col c&255).
#define ISSUE_TILE(t, slot)                                                   \
    {                                                                         \
        _Pragma("unroll")                                                     \
        for (int c = tid; c < CHUNKS; c += THREADS) {                         \
            int n = c >> 8, col = c & 255;                                    \
            cp_async16(sb_a + (uint32_t)((slot) * CHUNKS + c) * 16u,          \
                       (const void*)(V + ((long)n * NTILES + (t)) * ROW_F4 + col)); \
        }                                                                     \
        asm volatile("cp.async.commit_group;\n" ::: "memory");                \
    }

    int tile = blockIdx.x;
    int slot = 0;

    // Prologue: fill the pipeline — up to 3 tiles in flight.
    ISSUE_TILE(tile, 0)
    if (tile + GRID < NTILES)     ISSUE_TILE(tile + GRID, 1)
    if (tile + 2 * GRID < NTILES) ISSUE_TILE(tile + 2 * GRID, 2)

    while (tile < NTILES) {
        // Wait for tile i; keep i+1, i+2 groups flying.
        if (tile + 2 * GRID < NTILES)
            asm volatile("cp.async.wait_group 2;\n" ::: "memory");
        else if (tile + GRID < NTILES)
            asm volatile("cp.async.wait_group 1;\n" ::: "memory");
        else
            asm volatile("cp.async.wait_group 0;\n" ::: "memory");
        __syncthreads();   // B0: tile i fully visible

        const float4* cur = sbuf + slot * CHUNKS;

        // ---- Phase 1 (row-mapped): warp w owns row w (w < 13).
        if (wid < NN) {
            float tss = 0.f, tdp = 0.f;
            #pragma unroll
            for (int k = 0; k < 8; k++) {
                float4 x = cur[wid * ROW_F4 + k * 32 + lane];
                tss = fmaf(x.x, x.x, fmaf(x.y, x.y, fmaf(x.z, x.z, fmaf(x.w, x.w, tss))));
                tdp = fmaf(x.x, cw[k].x, fmaf(x.y, cw[k].y, fmaf(x.z, cw[k].z, fmaf(x.w, cw[k].w, tdp))));
            }
            #pragma unroll
            for (int off = 16; off > 0; off >>= 1) {
                tss += __shfl_xor_sync(0xFFFFFFFFu, tss, off);
                tdp += __shfl_xor_sync(0xFFFFFFFFu, tdp, off);
            }
            if (lane == 0)
                s_logit[wid] = rsqrtf(tss * (1.0f / DD) + EPS) * tdp;
        }
        __syncthreads();   // B1: logits valid; all cross-thread reads of slot done

        // ---- Softmax: per-warp, redundant (no extra barrier).
        float lv = (lane < NN) ? s_logit[lane] : -INFINITY;
        float mx = lv;
        #pragma unroll
        for (int off = 16; off > 0; off >>= 1)
            mx = fmaxf(mx, __shfl_xor_sync(0xFFFFFFFFu, mx, off));
        float e = (lane < NN) ? __expf(lv - mx) : 0.f;
        float sm = e;
        #pragma unroll
        for (int off = 16; off > 0; off >>= 1)
            sm += __shfl_xor_sync(0xFFFFFFFFu, sm, off);
        const float av = e * (1.0f / sm);     // alpha for depth = lane

        // ---- Phase 2 (column-mapped, float2): weighted sum + store.
        {
            const float2* cur2 = reinterpret_cast<const float2*>(cur);
            float2 o = make_float2(0.f, 0.f);
            #pragma unroll
            for (int n = 0; n < NN; n++) {
                float2 x = cur2[n * 512 + tid];
                float an = __shfl_sync(0xFFFFFFFFu, av, n);
                o.x = fmaf(an, x.x, o.x);
                o.y = fmaf(an, x.y, o.y);
            }
            reinterpret_cast<float2*>(out)[(long)tile * 512 + tid] = o;
        }

        // Refill this slot with tile i+3 (depth-3 ring keeps 2 tiles flying
        // through the whole compute span). Phase-2 reads of this slot are
        // this-thread-... cross-thread via float2 view? No: float2 cell
        // n*512+tid maps to bytes this thread may not have copied; but B1
        // only fenced phase-1. Need a barrier before overwrite:
        __syncthreads();   // B2: all phase-2 reads of this slot complete

        if (tile + 3 * GRID < NTILES) ISSUE_TILE(tile + 3 * GRID, slot)

        tile += GRID;
        slot = (slot == SLOTS - 1) ? 0 : slot + 1;
    }
#undef ISSUE_TILE
}

extern "C" void kernel_launch(void* const* d_in, const int* in_sizes, int n_in,
                              void* d_out, int out_size)
{
    const float4* V      = (const float4*)d_in[0];   // [13,2,2048,1024] f32
    const float4* rms_w  = (const float4*)d_in[1];   // [1024] f32
    const float4* w_proj = (const float4*)d_in[2];   // [1024] f32
    float4* out          = (float4*)d_out;           // [2,2048,1024] f32

    cudaFuncSetAttribute(attn_res_block_kernel,
                         cudaFuncAttributeMaxDynamicSharedMemorySize, SMEM_BYTES);

    attn_res_block_kernel<<<GRID, THREADS, SMEM_BYTES>>>(V, rms_w, w_proj, out);
}

// round 12
// speedup vs baseline: 1.0891x; 1.0891x over previous
#include <cuda_runtime.h>
#include <cuda_bf16.h>
#include <math.h>
#include <stdint.h>

// Problem constants
#define NN 13
#define BB 2
#define TT 2048
#define DD 1024
#define ROW_F4 (DD / 4)          // 256 float4 per row
#define NTILES (BB * TT)         // 4096
#define THREADS 256
#define GRID 304                 // 2 CTAs per SM
#define EPS 1.1920928955078125e-07f   // FLT_EPSILON

// Dynamic smem: 2 row buffers x NN x 256 float4 = 106496 B
#define BUF_F4      (NN * ROW_F4)
#define SMEM_BYTES  (2 * BUF_F4 * 16)

__device__ __forceinline__ void cp_async16(uint32_t smem_addr, const void* gptr) {
    asm volatile("cp.async.cg.shared.global [%0], [%1], 16;\n"
                 :: "r"(smem_addr), "l"(gptr) : "memory");
}

__global__ __launch_bounds__(THREADS, 2)
void attn_res_block_kernel(const float4* __restrict__ V,
                           const float4* __restrict__ rms_w,
                           const float4* __restrict__ w_proj,
                           float4* __restrict__ out)
{
    extern __shared__ float4 sbuf[];            // [2][NN][ROW_F4]
    __shared__ float s_logit[NN];

    const int tid  = threadIdx.x;
    const int lane = tid & 31;
    const int wid  = tid >> 5;                  // 0..7

    uint32_t sb_a;
    {
        uint64_t t;
        asm("cvta.to.shared.u64 %0, %1;" : "=l"(t) : "l"((void*)sbuf));
        sb_a = (uint32_t)t;
    }

    // Lane-indexed combined weight (rms_weight * w_proj), in registers.
    // Phase-1 row view: lane covers float4 columns k*32+lane, k=0..7.
    float4 cw[8];
    #pragma unroll
    for (int k = 0; k < 8; k++) {
        float4 a = rms_w[k * 32 + lane];
        float4 b = w_proj[k * 32 + lane];
        cw[k] = make_float4(a.x * b.x, a.y * b.y, a.z * b.z, a.w * b.w);
    }

    // Rows owned by this warp: r0 = wid, r1 = wid+8 (warps 0-4 only).
    const int r0 = wid;
    const int r1 = wid + 8;
    const bool has_r1 = (r1 < NN);

    // Warp-owned copy: warp w copies ONLY its rows, lane mapping col=j*32+lane
    // (identical to the phase-1 read mapping -> every byte this lane reads in
    // phase 1 was written by this lane's own cp.async; per-thread wait_group
    // is then sufficient, no CTA barrier before phase 1). Each j-step spans a
    // contiguous 512B warp-wide -> fully coalesced.
#define ISSUE_TILE(t, pbuf)                                                   \
    {                                                                         \
        const float4* gr0 = V + ((long)r0 * NTILES + (t)) * ROW_F4 + lane;    \
        uint32_t sr0 = sb_a + (uint32_t)(((pbuf) * NN + r0) * ROW_F4 + lane) * 16u; \
        _Pragma("unroll")                                                     \
        for (int j = 0; j < 8; j++)                                           \
            cp_async16(sr0 + (uint32_t)(j * 32) * 16u, (const void*)(gr0 + j * 32)); \
        if (has_r1) {                                                         \
            const float4* gr1 = V + ((long)r1 * NTILES + (t)) * ROW_F4 + lane; \
            uint32_t sr1 = sb_a + (uint32_t)(((pbuf) * NN + r1) * ROW_F4 + lane) * 16u; \
            _Pragma("unroll")                                                 \
            for (int j = 0; j < 8; j++)                                       \
                cp_async16(sr1 + (uint32_t)(j * 32) * 16u, (const void*)(gr1 + j * 32)); \
        }                                                                     \
        asm volatile("cp.async.commit_group;\n" ::: "memory");                \
    }

    int tile = blockIdx.x;
    int p = 0;

    // Prologue: two tiles in flight (one commit group per tile per thread).
    ISSUE_TILE(tile, 0)
    if (tile + GRID < NTILES) ISSUE_TILE(tile + GRID, 1)

    while (tile < NTILES) {
        // Per-warp wait: only THIS warp's rows for tile i must have landed.
        if (tile + GRID < NTILES)
            asm volatile("cp.async.wait_group 1;\n" ::: "memory");
        else
            asm volatile("cp.async.wait_group 0;\n" ::: "memory");

        const float4* cur = sbuf + p * BUF_F4;

        // ---- Phase 1 (warp-owned rows, no barrier needed before this):
        // conflict-free strided LDS of exactly the bytes this lane copied.
        #pragma unroll
        for (int rep = 0; rep < 2; rep++) {
            const int r = (rep == 0) ? r0 : r1;
            if (rep == 0 || has_r1) {
                float tss = 0.f, tdp = 0.f;
                #pragma unroll
                for (int k = 0; k < 8; k++) {
                    float4 x = cur[r * ROW_F4 + k * 32 + lane];
                    tss = fmaf(x.x, x.x, fmaf(x.y, x.y, fmaf(x.z, x.z, fmaf(x.w, x.w, tss))));
                    tdp = fmaf(x.x, cw[k].x, fmaf(x.y, cw[k].y, fmaf(x.z, cw[k].z, fmaf(x.w, cw[k].w, tdp))));
                }
                #pragma unroll
                for (int off = 16; off > 0; off >>= 1) {
                    tss += __shfl_xor_sync(0xFFFFFFFFu, tss, off);
                    tdp += __shfl_xor_sync(0xFFFFFFFFu, tdp, off);
                }
                if (lane == 0)
                    s_logit[r] = rsqrtf(tss * (1.0f / DD) + EPS) * tdp;
            }
        }
        __syncthreads();   // B1: every warp passed its wait + wrote its logits
                           // -> whole tile resident + all logits visible.

        // ---- Softmax: per-warp, redundant (no extra barrier).
        float lv = (lane < NN) ? s_logit[lane] : -INFINITY;
        float mx = lv;
        #pragma unroll
        for (int off = 16; off > 0; off >>= 1)
            mx = fmaxf(mx, __shfl_xor_sync(0xFFFFFFFFu, mx, off));
        float e = (lane < NN) ? __expf(lv - mx) : 0.f;
        float sm = e;
        #pragma unroll
        for (int off = 16; off > 0; off >>= 1)
            sm += __shfl_xor_sync(0xFFFFFFFFu, sm, off);
        const float av = e * (1.0f / sm);     // alpha for depth = lane

        // ---- Phase 2 (column-mapped): weighted sum; alphas via shuffle bcast.
        float4 o = make_float4(0.f, 0.f, 0.f, 0.f);
        #pragma unroll
        for (int n = 0; n < NN; n++) {
            float4 x = cur[n * ROW_F4 + tid];
            float an = __shfl_sync(0xFFFFFFFFu, av, n);
            o.x = fmaf(an, x.x, o.x);
            o.y = fmaf(an, x.y, o.y);
            o.z = fmaf(an, x.z, o.z);
            o.w = fmaf(an, x.w, o.w);
        }
        out[(long)tile * ROW_F4 + tid] = o;

        __syncthreads();   // B2: all cross-thread phase-2 reads of slot p done

        // Refill slot p with tile i+2 (this warp's rows only).
        if (tile + 2 * GRID < NTILES) ISSUE_TILE(tile + 2 * GRID, p)

        tile += GRID;
        p ^= 1;
    }
#undef ISSUE_TILE
}

extern "C" void kernel_launch(void* const* d_in, const int* in_sizes, int n_in,
                              void* d_out, int out_size)
{
    const float4* V      = (const float4*)d_in[0];   // [13,2,2048,1024] f32
    const float4* rms_w  = (const float4*)d_in[1];   // [1024] f32
    const float4* w_proj = (const float4*)d_in[2];   // [1024] f32
    float4* out          = (float4*)d_out;           // [2,2048,1024] f32

    cudaFuncSetAttribute(attn_res_block_kernel,
                         cudaFuncAttributeMaxDynamicSharedMemorySize, SMEM_BYTES);

    attn_res_block_kernel<<<GRID, THREADS, SMEM_BYTES>>>(V, rms_w, w_proj, out);
}

// round 13
// speedup vs baseline: 1.1319x; 1.0394x over previous
#include <cuda_runtime.h>
#include <cuda_bf16.h>
#include <math.h>
#include <stdint.h>

// Problem constants
#define NN 13
#define BB 2
#define TT 2048
#define DD 1024
#define ROW_F4 (DD / 4)          // 256 float4 per row
#define NTILES (BB * TT)         // 4096
#define CWARPS 8                 // compute warps
#define CTHREADS 256             // compute threads
#define THREADS 288              // + 1 producer warp
#define GRID 304                 // 2 CTAs per SM
#define EPS 1.1920928955078125e-07f   // FLT_EPSILON

#define BUF_F4      (NN * ROW_F4)
#define TILE_BYTES  (BUF_F4 * 16)        // 53248
#define SMEM_BYTES  (2 * TILE_BYTES)     // 106496

__device__ __forceinline__ uint32_t smem_u32(const void* p) {
    uint32_t a;
    asm("{ .reg .u64 t; cvta.to.shared.u64 t, %1; cvt.u32.u64 %0, t; }"
        : "=r"(a) : "l"(p));
    return a;
}
__device__ __forceinline__ void mbar_init(uint32_t m, uint32_t cnt) {
    asm volatile("mbarrier.init.shared.b64 [%0], %1;" :: "r"(m), "r"(cnt) : "memory");
}
__device__ __forceinline__ void mbar_expect_tx(uint32_t m, uint32_t bytes) {
    asm volatile("mbarrier.arrive.expect_tx.shared.b64 _, [%0], %1;"
                 :: "r"(m), "r"(bytes) : "memory");
}
__device__ __forceinline__ void mbar_arrive(uint32_t m) {
    asm volatile("mbarrier.arrive.shared.b64 _, [%0];" :: "r"(m) : "memory");
}
__device__ __forceinline__ void mbar_wait(uint32_t m, uint32_t parity) {
    asm volatile(
        "{\n\t.reg .pred P;\n\t"
        "WAIT_%=:\n\t"
        "mbarrier.try_wait.parity.acquire.cta.shared::cta.b64 P, [%0], %1, 0x989680;\n\t"
        "@P bra DONE_%=;\n\t"
        "bra WAIT_%=;\n\t"
        "DONE_%=:\n\t}"
        :: "r"(m), "r"(parity) : "memory");
}
// 1D bulk async copy gmem -> smem with transaction-count completion.
__device__ __forceinline__ void tma_1d(uint32_t dst, const void* src,
                                       uint32_t bytes, uint32_t mbar) {
    asm volatile(
        "cp.async.bulk.shared::cta.global.mbarrier::complete_tx::bytes [%0], [%1], %2, [%3];"
        :: "r"(dst), "l"(src), "r"(bytes), "r"(mbar) : "memory");
}

__global__ __launch_bounds__(THREADS, 2)
void attn_res_block_kernel(const float4* __restrict__ V,
                           const float4* __restrict__ rms_w,
                           const float4* __restrict__ w_proj,
                           float4* __restrict__ out)
{
    extern __shared__ float4 sbuf[];               // [2][NN][ROW_F4]
    __shared__ __align__(8) uint64_t mb_full[2];   // slot filled (tx-count)
    __shared__ __align__(8) uint64_t mb_empty[2];  // slot consumed (8 warps)
    __shared__ float s_logit[2][NN];               // per-slot (warp skew < 2 iters)

    const int tid  = threadIdx.x;
    const int lane = tid & 31;
    const int wid  = tid >> 5;                     // 0..8

    const uint32_t full_a  = smem_u32(&mb_full[0]);
    const uint32_t empty_a = smem_u32(&mb_empty[0]);
    const uint32_t sb_a    = smem_u32(sbuf);

    if (tid == 0) {
        mbar_init(full_a,      1);
        mbar_init(full_a + 8,  1);
        mbar_init(empty_a,     CWARPS);
        mbar_init(empty_a + 8, CWARPS);
        asm volatile("fence.proxy.async.shared::cta;" ::: "memory");
    }
    __syncthreads();

    // ================= Producer warp (wid == 8) =================
    if (wid == CWARPS) {
        if (lane == 0) {
            int pe0 = 0, pe1 = 0;
            int j = 0;
            for (int t = blockIdx.x; t < NTILES; t += GRID, j++) {
                const int s = j & 1;
                if (j >= 2) {                       // wait slot consumed
                    if (s == 0) { mbar_wait(empty_a,     pe0); pe0 ^= 1; }
                    else        { mbar_wait(empty_a + 8, pe1); pe1 ^= 1; }
                }
                mbar_expect_tx(full_a + s * 8, TILE_BYTES);
                #pragma unroll
                for (int n = 0; n < NN; n++)
                    tma_1d(sb_a + (uint32_t)(s * BUF_F4 + n * ROW_F4) * 16u,
                           (const void*)(V + ((long)n * NTILES + t) * ROW_F4),
                           (uint32_t)(ROW_F4 * 16), full_a + s * 8);
            }
        }
        return;   // producer warp exits when all tiles issued
    }

    // ================= Consumer warps (tid < 256) =================
    // Lane-indexed combined weight (rms_weight * w_proj), registers.
    float4 cw[8];
    #pragma unroll
    for (int k = 0; k < 8; k++) {
        float4 a = rms_w[k * 32 + lane];
        float4 b = w_proj[k * 32 + lane];
        cw[k] = make_float4(a.x * b.x, a.y * b.y, a.z * b.z, a.w * b.w);
    }

    int pf0 = 0, pf1 = 0;
    int j = 0;
    for (int tile = blockIdx.x; tile < NTILES; tile += GRID, j++) {
        const int s = j & 1;
        if (s == 0) { mbar_wait(full_a,     pf0); pf0 ^= 1; }
        else        { mbar_wait(full_a + 8, pf1); pf1 ^= 1; }

        const float4* cur = sbuf + s * BUF_F4;

        // ---- Phase 1 (row-mapped): warp w owns rows w and w+8.
        #pragma unroll
        for (int rep = 0; rep < 2; rep++) {
            const int r = wid + rep * 8;
            if (r < NN) {
                float tss = 0.f, tdp = 0.f;
                #pragma unroll
                for (int k = 0; k < 8; k++) {
                    float4 x = cur[r * ROW_F4 + k * 32 + lane];
                    tss = fmaf(x.x, x.x, fmaf(x.y, x.y, fmaf(x.z, x.z, fmaf(x.w, x.w, tss))));
                    tdp = fmaf(x.x, cw[k].x, fmaf(x.y, cw[k].y, fmaf(x.z, cw[k].z, fmaf(x.w, cw[k].w, tdp))));
                }
                #pragma unroll
                for (int off = 16; off > 0; off >>= 1) {
                    tss += __shfl_xor_sync(0xFFFFFFFFu, tss, off);
                    tdp += __shfl_xor_sync(0xFFFFFFFFu, tdp, off);
                }
                if (lane == 0)
                    s_logit[s][r] = rsqrtf(tss * (1.0f / DD) + EPS) * tdp;
            }
        }
        // B1: compute warps only (named barrier; producer excluded).
        asm volatile("bar.sync 1, %0;" :: "n"(CTHREADS) : "memory");

        // ---- Softmax: per-warp redundant; 13 values live in lanes 0..15
        // so 4 butterfly steps (8,4,2,1) suffice.
        float lv = (lane < NN) ? s_logit[s][lane] : -INFINITY;
        float mx = lv;
        #pragma unroll
        for (int off = 8; off > 0; off >>= 1)
            mx = fmaxf(mx, __shfl_xor_sync(0xFFFFFFFFu, mx, off));
        float e = (lane < NN) ? __expf(lv - mx) : 0.f;
        float sm = e;
        #pragma unroll
        for (int off = 8; off > 0; off >>= 1)
            sm += __shfl_xor_sync(0xFFFFFFFFu, sm, off);
        const float av = e * (1.0f / sm);        // alpha for depth = lane (0..12)

        // ---- Phase 2 (column-mapped): weighted sum; alphas via shuffle bcast.
        float4 o = make_float4(0.f, 0.f, 0.f, 0.f);
        #pragma unroll
        for (int n = 0; n < NN; n++) {
            float4 x = cur[n * ROW_F4 + tid];
            float an = __shfl_sync(0xFFFFFFFFu, av, n);
            o.x = fmaf(an, x.x, o.x);
            o.y = fmaf(an, x.y, o.y);
            o.z = fmaf(an, x.z, o.z);
            o.w = fmaf(an, x.w, o.w);
        }
        out[(long)tile * ROW_F4 + tid] = o;

        // This warp is done reading slot s (convergent code: all lanes past
        // their reads) -> non-blocking arrive; only the producer waits.
        if (lane == 0) mbar_arrive(empty_a + s * 8);
    }
}

extern "C" void kernel_launch(void* const* d_in, const int* in_sizes, int n_in,
                              void* d_out, int out_size)
{
    const float4* V      = (const float4*)d_in[0];   // [13,2,2048,1024] f32
    const float4* rms_w  = (const float4*)d_in[1];   // [1024] f32
    const float4* w_proj = (const float4*)d_in[2];   // [1024] f32
    float4* out          = (float4*)d_out;           // [2,2048,1024] f32

    cudaFuncSetAttribute(attn_res_block_kernel,
                         cudaFuncAttributeMaxDynamicSharedMemorySize, SMEM_BYTES);

    attn_res_block_kernel<<<GRID, THREADS, SMEM_BYTES>>>(V, rms_w, w_proj, out);
}